// round 12
// baseline (speedup 1.0000x reference)
#include <cuda_runtime.h>

#define LCOLS 4096
#define NSTAGES 12
#define RROWS 8
#define NPAIR 4
#define TPB 1024
#define NBATCH 8192

typedef unsigned long long ull;

// Precomputed duplicated weights: per (stage, j), 16 bytes = {(w0,w0),(w1,w1)}.
__device__ ull g_Wd[NSTAGES * LCOLS * 2];

// ---- packed f32x2 helpers (FFMA2/FMUL2 are PTX-only on sm_103a) ----
__device__ __forceinline__ ull pack2(float a, float b) {
    ull r; asm("mov.b64 %0, {%1, %2};" : "=l"(r) : "f"(a), "f"(b)); return r;
}
__device__ __forceinline__ void unpack2(ull v, float& a, float& b) {
    asm("mov.b64 {%0, %1}, %2;" : "=f"(a), "=f"(b) : "l"(v));
}
__device__ __forceinline__ ull mul2(ull a, ull b) {
    ull d; asm("mul.rn.f32x2 %0, %1, %2;" : "=l"(d) : "l"(a), "l"(b)); return d;
}
__device__ __forceinline__ ull fma2(ull a, ull b, ull c) {
    ull d; asm("fma.rn.f32x2 %0, %1, %2, %3;" : "=l"(d) : "l"(a), "l"(b), "l"(c)); return d;
}

// one LDG.128: both duplicated weight ulls for (stage s, column j)
__device__ __forceinline__ void ldw(int s, int j, ull& W0, ull& W1) {
    const ulonglong2 v = __ldg(reinterpret_cast<const ulonglong2*>(
        &g_Wd[2 * (s * LCOLS + j)]));
    W0 = v.x; W1 = v.y;
}

// packed butterfly on reg-bit D over 4 regs; weights pre-duplicated ulls
template <int D>
__device__ __forceinline__ void bfly2(ull Y[NPAIR][4],
                                      const ull* W0, const ull* W1) {
    #pragma unroll
    for (int c = 0; c < 4; ++c) {
        if (c & D) continue;
        const int ch = c | D;
        #pragma unroll
        for (int p = 0; p < NPAIR; ++p) {
            const ull a = Y[p][c], b = Y[p][ch];
            Y[p][c]  = fma2(W0[c],  a, mul2(W1[c],  b));
            Y[p][ch] = fma2(W0[ch], b, mul2(W1[ch], a));
        }
    }
}

// swap roles of register bit MC and lane bit ML (half-exchange, 2 shfl / 4 regs)
template <int MC, int ML>
__device__ __forceinline__ void bitswap2(ull* yr, bool lo) {
    #pragma unroll
    for (int c = 0; c < 4; ++c) {
        if (c & MC) continue;
        const int ch = c | MC;
        ull send = lo ? yr[ch] : yr[c];
        ull recv = __shfl_xor_sync(0xffffffffu, send, ML);
        if (lo) yr[ch] = recv; else yr[c] = recv;
    }
}

// shared-memory physical swizzle: bank bit 4 ^= address bit 11
__device__ __forceinline__ int phys(int a) {
    return a ^ (((a >> 11) & 1) << 4);
}

// prep: expand W into duplicated packed form
__global__ void prep_weights(const float* __restrict__ W) {
    const int i = blockIdx.x * blockDim.x + threadIdx.x;   // (s*LCOLS + j)
    if (i < NSTAGES * LCOLS) {
        const float2 ww = __ldg(reinterpret_cast<const float2*>(W) + i);
        g_Wd[2 * i]     = pack2(ww.x, ww.x);
        g_Wd[2 * i + 1] = pack2(ww.y, ww.y);
    }
}

// y[j] <- W[s][j][0]*y[j] + W[s][j][1]*y[j ^ (1<<s)]
// TPB=1024: thread owns 4 cols (2 reg bits), row-pairs packed in f32x2,
// smem as 64-bit words, weights pre-duplicated (1 LDG.128 per column-stage).
// Phase 1 (stages 0..6): regs j[0:1] -> swapA j[2:3] -> swapB j[4:5] -> swapC j[6].
// Round 1 (stages 7..8): smem gather regs=j[7:8], in-place writeback.
// Round 2 (stages 9..11): gather regs=j[9:10]; stages 9,10 in-reg; bitswap
// j9<->j11 then stage 11 in-reg. Direct global store (64B runs).
__global__ __launch_bounds__(TPB, 1)
void butterfly_kernel(const float* __restrict__ x,
                      float* __restrict__ out)
{
    extern __shared__ ull sm2[];   // NPAIR * LCOLS ulls = 128 KB
    const int tid  = threadIdx.x;
    const int row0 = blockIdx.x * RROWS;
    const int l    = tid & 31;
    const int w    = tid >> 5;
    const int j0   = tid * 4;
    const bool lo1  = (l & 1) == 0;
    const bool lo2  = (l & 2) == 0;
    const bool lo4  = (l & 4) == 0;
    const bool lo8  = (l & 8) == 0;
    const bool lo16 = (l & 16) == 0;

    ull Y[NPAIR][4];

    // ---- load 8 rows x 4 contiguous cols, pack row-pairs ----
    #pragma unroll
    for (int p = 0; p < NPAIR; ++p) {
        float4 a0 = __ldg(reinterpret_cast<const float4*>(
            x + (size_t)(row0 + 2 * p) * LCOLS + j0));
        float4 a1 = __ldg(reinterpret_cast<const float4*>(
            x + (size_t)(row0 + 2 * p + 1) * LCOLS + j0));
        Y[p][0] = pack2(a0.x, a1.x); Y[p][1] = pack2(a0.y, a1.y);
        Y[p][2] = pack2(a0.z, a1.z); Y[p][3] = pack2(a0.w, a1.w);
    }

    ull W0[4], W1[4];

    // ---- stages 0,1 : regs = j[0:1] ----
    #pragma unroll
    for (int s = 0; s < 2; ++s) {
        #pragma unroll
        for (int c = 0; c < 4; ++c) ldw(s, j0 + c, W0[c], W1[c]);
        if (s == 0) bfly2<1>(Y, W0, W1); else bfly2<2>(Y, W0, W1);
    }

    // ---- swap A : regs = j[2:3] ; stages 2,3 ----
    #pragma unroll
    for (int p = 0; p < NPAIR; ++p) {
        bitswap2<1, 1>(Y[p], lo1);
        bitswap2<2, 2>(Y[p], lo2);
    }
    const int jA = (l & 3) + ((l >> 2) & 7) * 16 + w * 128;   // j = jA + 4c
    #pragma unroll
    for (int s = 2; s < 4; ++s) {
        #pragma unroll
        for (int c = 0; c < 4; ++c) ldw(s, jA + 4 * c, W0[c], W1[c]);
        if (s == 2) bfly2<1>(Y, W0, W1); else bfly2<2>(Y, W0, W1);
    }

    // ---- swap B : regs = j[4:5] ; stages 4,5 ----
    #pragma unroll
    for (int p = 0; p < NPAIR; ++p) {
        bitswap2<1, 4>(Y[p], lo4);
        bitswap2<2, 8>(Y[p], lo8);
    }
    const int jB = (l & 15) + ((l >> 4) & 1) * 64 + w * 128;  // j = jB + 16c
    #pragma unroll
    for (int s = 4; s < 6; ++s) {
        #pragma unroll
        for (int c = 0; c < 4; ++c) ldw(s, jB + 16 * c, W0[c], W1[c]);
        if (s == 4) bfly2<1>(Y, W0, W1); else bfly2<2>(Y, W0, W1);
    }

    // ---- swap C : reg bit0 = j[6] (bit1 stays j[5]) ; stage 6 ----
    #pragma unroll
    for (int p = 0; p < NPAIR; ++p)
        bitswap2<1, 16>(Y[p], lo16);
    const int jC = (l & 15) + ((l >> 4) & 1) * 16 + w * 128;
    // j(c) = jC + (c&1)*64 + ((c>>1)&1)*32
    {
        #pragma unroll
        for (int c = 0; c < 4; ++c)
            ldw(6, jC + ((c & 1) << 6) + (((c >> 1) & 1) << 5), W0[c], W1[c]);
        bfly2<1>(Y, W0, W1);
    }

    // ---- store packed columns to smem at phys(j), 64-bit STS ----
    {
        int sj[4];
        #pragma unroll
        for (int c = 0; c < 4; ++c)
            sj[c] = phys(jC + ((c & 1) << 6) + (((c >> 1) & 1) << 5));
        #pragma unroll
        for (int p = 0; p < NPAIR; ++p)
            #pragma unroll
            for (int c = 0; c < 4; ++c)
                sm2[p * LCOLS + sj[c]] = Y[p][c];
    }
    __syncthreads();

    // ---- round 1 : stages 7,8 (regs = j[7:8]) ----
    // lanes = j[0:4]; warp bits = (j5, j6, j9, j10, j11)
    const int base1 = l + (w & 1) * 32 + ((w >> 1) & 1) * 64
                    + ((w >> 2) & 1) * 512 + ((w >> 3) & 1) * 1024
                    + ((w >> 4) & 1) * 2048;            // j = base1 + 128c
    const int pb1 = phys(base1);                        // bit11 const, no carry
    {
        ull V[NPAIR][4];
        #pragma unroll
        for (int p = 0; p < NPAIR; ++p)
            #pragma unroll
            for (int c = 0; c < 4; ++c)
                V[p][c] = sm2[p * LCOLS + pb1 + 128 * c];

        #pragma unroll
        for (int s = 7; s < 9; ++s) {
            #pragma unroll
            for (int c = 0; c < 4; ++c) ldw(s, base1 + 128 * c, W0[c], W1[c]);
            if (s == 7) bfly2<1>(V, W0, W1); else bfly2<2>(V, W0, W1);
        }

        // in-place writeback (each element owned by exactly this thread)
        #pragma unroll
        for (int p = 0; p < NPAIR; ++p)
            #pragma unroll
            for (int c = 0; c < 4; ++c)
                sm2[p * LCOLS + pb1 + 128 * c] = V[p][c];
    }
    __syncthreads();

    // ---- round 2 : stages 9,10 (regs = j[9:10]); swap -> stage 11 in-reg ----
    // lanes = (j0..j3, j11); warp bits = j[4:8]
    const int base2 = (l & 15) + w * 16 + ((l >> 4) & 1) * 2048;  // j = base2 + 512c
    const int pb2 = base2 ^ (((l >> 4) & 1) << 4);                // phys, no carry
    {
        ull V[NPAIR][4];
        #pragma unroll
        for (int p = 0; p < NPAIR; ++p)
            #pragma unroll
            for (int c = 0; c < 4; ++c)
                V[p][c] = sm2[p * LCOLS + pb2 + 512 * c];

        #pragma unroll
        for (int s = 9; s < 11; ++s) {
            #pragma unroll
            for (int c = 0; c < 4; ++c) ldw(s, base2 + 512 * c, W0[c], W1[c]);
            if (s == 9) bfly2<1>(V, W0, W1); else bfly2<2>(V, W0, W1);
        }

        // swap reg bit0 (j9) <-> lane bit4 (j11); then stage 11 in-register
        #pragma unroll
        for (int p = 0; p < NPAIR; ++p)
            bitswap2<1, 16>(V[p], lo16);
        // new layout: c0 = j11 (offset 2048), c1 = j10 (offset 1024), l4 = j9
        const int b11m = (l & 15) + w * 16 + ((l >> 4) & 1) * 512;
        {
            #pragma unroll
            for (int c = 0; c < 4; ++c)
                ldw(11, b11m + ((c & 1) << 11) + (((c >> 1) & 1) << 10),
                    W0[c], W1[c]);
            bfly2<1>(V, W0, W1);
        }

        // direct global store: lanes 0-15 / 16-31 each cover 64B runs
        #pragma unroll
        for (int p = 0; p < NPAIR; ++p) {
            float* op0 = out + (size_t)(row0 + 2 * p) * LCOLS + b11m;
            float* op1 = out + (size_t)(row0 + 2 * p + 1) * LCOLS + b11m;
            #pragma unroll
            for (int c = 0; c < 4; ++c) {
                const int off = ((c & 1) << 11) + (((c >> 1) & 1) << 10);
                float a, b;
                unpack2(V[p][c], a, b);
                op0[off] = a;
                op1[off] = b;
            }
        }
    }
}

extern "C" void kernel_launch(void* const* d_in, const int* in_sizes, int n_in,
                              void* d_out, int out_size) {
    const float* x;
    const float* W;
    if (in_sizes[0] == NSTAGES * LCOLS * 2) {   // W has 98304 elements
        W = (const float*)d_in[0];
        x = (const float*)d_in[1];
    } else {
        x = (const float*)d_in[0];
        W = (const float*)d_in[1];
    }
    float* out = (float*)d_out;

    prep_weights<<<(NSTAGES * LCOLS + 255) / 256, 256>>>(W);

    const int smem_bytes = NPAIR * LCOLS * sizeof(ull);  // 128 KB
    cudaFuncSetAttribute(butterfly_kernel,
                         cudaFuncAttributeMaxDynamicSharedMemorySize, smem_bytes);
    butterfly_kernel<<<NBATCH / RROWS, TPB, smem_bytes>>>(x, out);
}

// round 13
// speedup vs baseline: 1.1631x; 1.1631x over previous
#include <cuda_runtime.h>

#define LCOLS 4096
#define NSTAGES 12
#define RROWS 8
#define NPAIR 4
#define TPB 1024
#define NBATCH 8192

typedef unsigned long long ull;

// ---- packed f32x2 helpers (FFMA2/FMUL2 are PTX-only on sm_103a) ----
__device__ __forceinline__ ull pack2(float a, float b) {
    ull r; asm("mov.b64 %0, {%1, %2};" : "=l"(r) : "f"(a), "f"(b)); return r;
}
__device__ __forceinline__ void unpack2(ull v, float& a, float& b) {
    asm("mov.b64 {%0, %1}, %2;" : "=f"(a), "=f"(b) : "l"(v));
}
__device__ __forceinline__ ull dup2(float a) { return pack2(a, a); }
__device__ __forceinline__ ull mul2(ull a, ull b) {
    ull d; asm("mul.rn.f32x2 %0, %1, %2;" : "=l"(d) : "l"(a), "l"(b)); return d;
}
__device__ __forceinline__ ull fma2(ull a, ull b, ull c) {
    ull d; asm("fma.rn.f32x2 %0, %1, %2, %3;" : "=l"(d) : "l"(a), "l"(b), "l"(c)); return d;
}

// packed butterfly on reg-bit D over 4 regs; weights shared by both packed rows
template <int D>
__device__ __forceinline__ void bfly2(ull Y[NPAIR][4],
                                      const float* w0, const float* w1) {
    #pragma unroll
    for (int c = 0; c < 4; ++c) {
        if (c & D) continue;
        const int ch = c | D;
        const ull W0l = dup2(w0[c]),  W1l = dup2(w1[c]);
        const ull W0h = dup2(w0[ch]), W1h = dup2(w1[ch]);
        #pragma unroll
        for (int p = 0; p < NPAIR; ++p) {
            const ull a = Y[p][c], b = Y[p][ch];
            Y[p][c]  = fma2(W0l, a, mul2(W1l, b));
            Y[p][ch] = fma2(W0h, b, mul2(W1h, a));
        }
    }
}

// swap roles of register bit MC and lane bit ML (half-exchange, 2 shfl / 4 regs)
template <int MC, int ML>
__device__ __forceinline__ void bitswap2(ull* yr, bool lo) {
    #pragma unroll
    for (int c = 0; c < 4; ++c) {
        if (c & MC) continue;
        const int ch = c | MC;
        ull send = lo ? yr[ch] : yr[c];
        ull recv = __shfl_xor_sync(0xffffffffu, send, ML);
        if (lo) yr[ch] = recv; else yr[c] = recv;
    }
}

// shared-memory physical swizzle: bank bit 4 ^= address bit 11
__device__ __forceinline__ int phys(int a) {
    return a ^ (((a >> 11) & 1) << 4);
}

// y[j] <- W[s][j][0]*y[j] + W[s][j][1]*y[j ^ (1<<s)]
// TPB=1024: thread owns 4 cols (2 reg bits), row-pairs packed in f32x2,
// smem accessed as 64-bit words.
// Phase 1 (stages 0..6): regs j[0:1] -> swapA j[2:3] -> swapB j[4:5] -> swapC j[6].
// Round 1 (stages 7..8): smem gather regs=j[7:8], in-place writeback.
// Round 2 (stages 9..11): gather regs=j[9:10]; stages 9,10 in-reg; bitswap
// j9<->j11 then stage 11 in-reg. Direct global store (64B runs).
__global__ __launch_bounds__(TPB, 1)
void butterfly_kernel(const float* __restrict__ x,
                      const float* __restrict__ W,
                      float* __restrict__ out)
{
    extern __shared__ ull sm2[];   // NPAIR * LCOLS ulls = 128 KB
    const int tid  = threadIdx.x;
    const int row0 = blockIdx.x * RROWS;
    const int l    = tid & 31;
    const int w    = tid >> 5;
    const int j0   = tid * 4;
    const bool lo1  = (l & 1) == 0;
    const bool lo2  = (l & 2) == 0;
    const bool lo4  = (l & 4) == 0;
    const bool lo8  = (l & 8) == 0;
    const bool lo16 = (l & 16) == 0;

    ull Y[NPAIR][4];

    // ---- load 8 rows x 4 contiguous cols, pack row-pairs ----
    #pragma unroll
    for (int p = 0; p < NPAIR; ++p) {
        float4 a0 = __ldg(reinterpret_cast<const float4*>(
            x + (size_t)(row0 + 2 * p) * LCOLS + j0));
        float4 a1 = __ldg(reinterpret_cast<const float4*>(
            x + (size_t)(row0 + 2 * p + 1) * LCOLS + j0));
        Y[p][0] = pack2(a0.x, a1.x); Y[p][1] = pack2(a0.y, a1.y);
        Y[p][2] = pack2(a0.z, a1.z); Y[p][3] = pack2(a0.w, a1.w);
    }

    float w0[4], w1[4];

    // ---- stages 0,1 : regs = j[0:1], weights 2x float4 contiguous ----
    #pragma unroll
    for (int s = 0; s < 2; ++s) {
        const float4* wp = reinterpret_cast<const float4*>(
            W + (size_t)s * (LCOLS * 2) + j0 * 2);
        float4 wA = __ldg(wp), wB = __ldg(wp + 1);
        w0[0]=wA.x; w1[0]=wA.y; w0[1]=wA.z; w1[1]=wA.w;
        w0[2]=wB.x; w1[2]=wB.y; w0[3]=wB.z; w1[3]=wB.w;
        if (s == 0) bfly2<1>(Y, w0, w1); else bfly2<2>(Y, w0, w1);
    }

    // ---- swap A : regs = j[2:3] ; stages 2,3 ----
    #pragma unroll
    for (int p = 0; p < NPAIR; ++p) {
        bitswap2<1, 1>(Y[p], lo1);
        bitswap2<2, 2>(Y[p], lo2);
    }
    const int jA = (l & 3) + ((l >> 2) & 7) * 16 + w * 128;   // j = jA + 4c
    #pragma unroll
    for (int s = 2; s < 4; ++s) {
        #pragma unroll
        for (int c = 0; c < 4; ++c) {
            const float2 ww = __ldg(reinterpret_cast<const float2*>(
                W + (size_t)s * (LCOLS * 2) + 2 * (jA + 4 * c)));
            w0[c] = ww.x; w1[c] = ww.y;
        }
        if (s == 2) bfly2<1>(Y, w0, w1); else bfly2<2>(Y, w0, w1);
    }

    // ---- swap B : regs = j[4:5] ; stages 4,5 ----
    #pragma unroll
    for (int p = 0; p < NPAIR; ++p) {
        bitswap2<1, 4>(Y[p], lo4);
        bitswap2<2, 8>(Y[p], lo8);
    }
    const int jB = (l & 15) + ((l >> 4) & 1) * 64 + w * 128;  // j = jB + 16c
    #pragma unroll
    for (int s = 4; s < 6; ++s) {
        #pragma unroll
        for (int c = 0; c < 4; ++c) {
            const float2 ww = __ldg(reinterpret_cast<const float2*>(
                W + (size_t)s * (LCOLS * 2) + 2 * (jB + 16 * c)));
            w0[c] = ww.x; w1[c] = ww.y;
        }
        if (s == 4) bfly2<1>(Y, w0, w1); else bfly2<2>(Y, w0, w1);
    }

    // ---- swap C : reg bit0 = j[6] (bit1 stays j[5]) ; stage 6 ----
    #pragma unroll
    for (int p = 0; p < NPAIR; ++p)
        bitswap2<1, 16>(Y[p], lo16);
    const int jC = (l & 15) + ((l >> 4) & 1) * 16 + w * 128;
    // j(c) = jC + (c&1)*64 + ((c>>1)&1)*32
    {
        #pragma unroll
        for (int c = 0; c < 4; ++c) {
            const int jb = jC + ((c & 1) << 6) + (((c >> 1) & 1) << 5);
            const float2 ww = __ldg(reinterpret_cast<const float2*>(
                W + (size_t)6 * (LCOLS * 2) + 2 * jb));
            w0[c] = ww.x; w1[c] = ww.y;
        }
        bfly2<1>(Y, w0, w1);
    }

    // ---- store packed columns to smem at phys(j), 64-bit STS ----
    {
        int sj[4];
        #pragma unroll
        for (int c = 0; c < 4; ++c)
            sj[c] = phys(jC + ((c & 1) << 6) + (((c >> 1) & 1) << 5));
        #pragma unroll
        for (int p = 0; p < NPAIR; ++p)
            #pragma unroll
            for (int c = 0; c < 4; ++c)
                sm2[p * LCOLS + sj[c]] = Y[p][c];
    }
    __syncthreads();

    // ---- round 1 : stages 7,8 (regs = j[7:8]) ----
    // lanes = j[0:4]; warp bits = (j5, j6, j9, j10, j11)
    const int base1 = l + (w & 1) * 32 + ((w >> 1) & 1) * 64
                    + ((w >> 2) & 1) * 512 + ((w >> 3) & 1) * 1024
                    + ((w >> 4) & 1) * 2048;            // j = base1 + 128c
    const int pb1 = phys(base1);                        // bit11 const, no carry
    {
        ull V[NPAIR][4];
        #pragma unroll
        for (int p = 0; p < NPAIR; ++p)
            #pragma unroll
            for (int c = 0; c < 4; ++c)
                V[p][c] = sm2[p * LCOLS + pb1 + 128 * c];

        #pragma unroll
        for (int s = 7; s < 9; ++s) {
            #pragma unroll
            for (int c = 0; c < 4; ++c) {
                const float2 ww = __ldg(reinterpret_cast<const float2*>(
                    W + (size_t)s * (LCOLS * 2) + 2 * (base1 + 128 * c)));
                w0[c] = ww.x; w1[c] = ww.y;
            }
            if (s == 7) bfly2<1>(V, w0, w1); else bfly2<2>(V, w0, w1);
        }

        // in-place writeback (each element owned by exactly this thread)
        #pragma unroll
        for (int p = 0; p < NPAIR; ++p)
            #pragma unroll
            for (int c = 0; c < 4; ++c)
                sm2[p * LCOLS + pb1 + 128 * c] = V[p][c];
    }
    __syncthreads();

    // ---- round 2 : stages 9,10 (regs = j[9:10]); swap -> stage 11 in-reg ----
    // lanes = (j0..j3, j11); warp bits = j[4:8]
    const int base2 = (l & 15) + w * 16 + ((l >> 4) & 1) * 2048;  // j = base2 + 512c
    const int pb2 = base2 ^ (((l >> 4) & 1) << 4);                // phys, no carry
    {
        ull V[NPAIR][4];
        #pragma unroll
        for (int p = 0; p < NPAIR; ++p)
            #pragma unroll
            for (int c = 0; c < 4; ++c)
                V[p][c] = sm2[p * LCOLS + pb2 + 512 * c];

        #pragma unroll
        for (int s = 9; s < 11; ++s) {
            #pragma unroll
            for (int c = 0; c < 4; ++c) {
                const float2 ww = __ldg(reinterpret_cast<const float2*>(
                    W + (size_t)s * (LCOLS * 2) + 2 * (base2 + 512 * c)));
                w0[c] = ww.x; w1[c] = ww.y;
            }
            if (s == 9) bfly2<1>(V, w0, w1); else bfly2<2>(V, w0, w1);
        }

        // swap reg bit0 (j9) <-> lane bit4 (j11); then stage 11 in-register
        #pragma unroll
        for (int p = 0; p < NPAIR; ++p)
            bitswap2<1, 16>(V[p], lo16);
        // new layout: c0 = j11 (offset 2048), c1 = j10 (offset 1024), l4 = j9
        const int b11m = (l & 15) + w * 16 + ((l >> 4) & 1) * 512;
        {
            #pragma unroll
            for (int c = 0; c < 4; ++c) {
                const int jb = b11m + ((c & 1) << 11) + (((c >> 1) & 1) << 10);
                const float2 ww = __ldg(reinterpret_cast<const float2*>(
                    W + (size_t)11 * (LCOLS * 2) + 2 * jb));
                w0[c] = ww.x; w1[c] = ww.y;
            }
            bfly2<1>(V, w0, w1);
        }

        // direct global store: lanes 0-15 / 16-31 each cover 64B runs
        #pragma unroll
        for (int p = 0; p < NPAIR; ++p) {
            float* op0 = out + (size_t)(row0 + 2 * p) * LCOLS + b11m;
            float* op1 = out + (size_t)(row0 + 2 * p + 1) * LCOLS + b11m;
            #pragma unroll
            for (int c = 0; c < 4; ++c) {
                const int off = ((c & 1) << 11) + (((c >> 1) & 1) << 10);
                float a, b;
                unpack2(V[p][c], a, b);
                op0[off] = a;
                op1[off] = b;
            }
        }
    }
}

extern "C" void kernel_launch(void* const* d_in, const int* in_sizes, int n_in,
                              void* d_out, int out_size) {
    const float* x;
    const float* W;
    if (in_sizes[0] == NSTAGES * LCOLS * 2) {   // W has 98304 elements
        W = (const float*)d_in[0];
        x = (const float*)d_in[1];
    } else {
        x = (const float*)d_in[0];
        W = (const float*)d_in[1];
    }
    float* out = (float*)d_out;

    const int smem_bytes = NPAIR * LCOLS * sizeof(ull);  // 128 KB
    cudaFuncSetAttribute(butterfly_kernel,
                         cudaFuncAttributeMaxDynamicSharedMemorySize, smem_bytes);
    butterfly_kernel<<<NBATCH / RROWS, TPB, smem_bytes>>>(x, W, out);
}

// round 14
// speedup vs baseline: 1.1884x; 1.0217x over previous
#include <cuda_runtime.h>

#define LCOLS 4096
#define NSTAGES 12
#define RROWS 8
#define NPAIR 4
#define TPB 1024
#define NBATCH 8192

typedef unsigned long long ull;

// ---- packed f32x2 helpers (FFMA2/FMUL2 are PTX-only on sm_103a) ----
__device__ __forceinline__ ull pack2(float a, float b) {
    ull r; asm("mov.b64 %0, {%1, %2};" : "=l"(r) : "f"(a), "f"(b)); return r;
}
__device__ __forceinline__ void unpack2(ull v, float& a, float& b) {
    asm("mov.b64 {%0, %1}, %2;" : "=f"(a), "=f"(b) : "l"(v));
}
__device__ __forceinline__ ull dup2(float a) { return pack2(a, a); }
__device__ __forceinline__ ull mul2(ull a, ull b) {
    ull d; asm("mul.rn.f32x2 %0, %1, %2;" : "=l"(d) : "l"(a), "l"(b)); return d;
}
__device__ __forceinline__ ull fma2(ull a, ull b, ull c) {
    ull d; asm("fma.rn.f32x2 %0, %1, %2, %3;" : "=l"(d) : "l"(a), "l"(b), "l"(c)); return d;
}

// packed butterfly on reg-bit D over 4 regs; weights shared by both packed rows
template <int D>
__device__ __forceinline__ void bfly2(ull Y[NPAIR][4],
                                      const float* w0, const float* w1) {
    #pragma unroll
    for (int c = 0; c < 4; ++c) {
        if (c & D) continue;
        const int ch = c | D;
        const ull W0l = dup2(w0[c]),  W1l = dup2(w1[c]);
        const ull W0h = dup2(w0[ch]), W1h = dup2(w1[ch]);
        #pragma unroll
        for (int p = 0; p < NPAIR; ++p) {
            const ull a = Y[p][c], b = Y[p][ch];
            Y[p][c]  = fma2(W0l, a, mul2(W1l, b));
            Y[p][ch] = fma2(W0h, b, mul2(W1h, a));
        }
    }
}

// swap roles of register bit MC and lane bit ML (half-exchange, 2 shfl / 4 regs)
template <int MC, int ML>
__device__ __forceinline__ void bitswap2(ull* yr, bool lo) {
    #pragma unroll
    for (int c = 0; c < 4; ++c) {
        if (c & MC) continue;
        const int ch = c | MC;
        ull send = lo ? yr[ch] : yr[c];
        ull recv = __shfl_xor_sync(0xffffffffu, send, ML);
        if (lo) yr[ch] = recv; else yr[c] = recv;
    }
}

// shared-memory physical swizzle: bank bit 4 ^= address bit 11
__device__ __forceinline__ int phys(int a) {
    return a ^ (((a >> 11) & 1) << 4);
}

// y[j] <- W[s][j][0]*y[j] + W[s][j][1]*y[j ^ (1<<s)]
// TPB=1024, thread owns 4 cols, row-pairs packed in f32x2, 64-bit smem words.
// Weight loads software-pipelined: two stages' weights issued back-to-back;
// round weights hoisted ABOVE each __syncthreads (ptxas won't hoist over BAR).
__global__ __launch_bounds__(TPB, 1)
void butterfly_kernel(const float* __restrict__ x,
                      const float* __restrict__ W,
                      float* __restrict__ out)
{
    extern __shared__ ull sm2[];   // NPAIR * LCOLS ulls = 128 KB
    const int tid  = threadIdx.x;
    const int row0 = blockIdx.x * RROWS;
    const int l    = tid & 31;
    const int w    = tid >> 5;
    const int j0   = tid * 4;
    const bool lo1  = (l & 1) == 0;
    const bool lo2  = (l & 2) == 0;
    const bool lo4  = (l & 4) == 0;
    const bool lo8  = (l & 8) == 0;
    const bool lo16 = (l & 16) == 0;

    ull Y[NPAIR][4];

    // ---- load 8 rows x 4 contiguous cols, pack row-pairs ----
    #pragma unroll
    for (int p = 0; p < NPAIR; ++p) {
        float4 a0 = __ldg(reinterpret_cast<const float4*>(
            x + (size_t)(row0 + 2 * p) * LCOLS + j0));
        float4 a1 = __ldg(reinterpret_cast<const float4*>(
            x + (size_t)(row0 + 2 * p + 1) * LCOLS + j0));
        Y[p][0] = pack2(a0.x, a1.x); Y[p][1] = pack2(a0.y, a1.y);
        Y[p][2] = pack2(a0.z, a1.z); Y[p][3] = pack2(a0.w, a1.w);
    }

    float w0a[4], w1a[4], w0b[4], w1b[4];

    // ---- stages 0,1 : regs = j[0:1]; both stages' weights issued first ----
    {
        const float4* wp0 = reinterpret_cast<const float4*>(W + (size_t)j0 * 2);
        const float4* wp1 = reinterpret_cast<const float4*>(
            W + (size_t)1 * (LCOLS * 2) + j0 * 2);
        float4 A0 = __ldg(wp0), B0 = __ldg(wp0 + 1);
        float4 A1 = __ldg(wp1), B1 = __ldg(wp1 + 1);
        w0a[0]=A0.x; w1a[0]=A0.y; w0a[1]=A0.z; w1a[1]=A0.w;
        w0a[2]=B0.x; w1a[2]=B0.y; w0a[3]=B0.z; w1a[3]=B0.w;
        w0b[0]=A1.x; w1b[0]=A1.y; w0b[1]=A1.z; w1b[1]=A1.w;
        w0b[2]=B1.x; w1b[2]=B1.y; w0b[3]=B1.z; w1b[3]=B1.w;
        bfly2<1>(Y, w0a, w1a);
        bfly2<2>(Y, w0b, w1b);
    }

    // ---- swap A : regs = j[2:3] ; stages 2,3 (weights paired) ----
    #pragma unroll
    for (int p = 0; p < NPAIR; ++p) {
        bitswap2<1, 1>(Y[p], lo1);
        bitswap2<2, 2>(Y[p], lo2);
    }
    const int jA = (l & 3) + ((l >> 2) & 7) * 16 + w * 128;   // j = jA + 4c
    {
        #pragma unroll
        for (int c = 0; c < 4; ++c) {
            const float2 wwa = __ldg(reinterpret_cast<const float2*>(
                W + (size_t)2 * (LCOLS * 2) + 2 * (jA + 4 * c)));
            const float2 wwb = __ldg(reinterpret_cast<const float2*>(
                W + (size_t)3 * (LCOLS * 2) + 2 * (jA + 4 * c)));
            w0a[c] = wwa.x; w1a[c] = wwa.y;
            w0b[c] = wwb.x; w1b[c] = wwb.y;
        }
        bfly2<1>(Y, w0a, w1a);
        bfly2<2>(Y, w0b, w1b);
    }

    // ---- swap B : regs = j[4:5] ; stages 4,5 (weights paired) ----
    #pragma unroll
    for (int p = 0; p < NPAIR; ++p) {
        bitswap2<1, 4>(Y[p], lo4);
        bitswap2<2, 8>(Y[p], lo8);
    }
    const int jB = (l & 15) + ((l >> 4) & 1) * 64 + w * 128;  // j = jB + 16c
    {
        #pragma unroll
        for (int c = 0; c < 4; ++c) {
            const float2 wwa = __ldg(reinterpret_cast<const float2*>(
                W + (size_t)4 * (LCOLS * 2) + 2 * (jB + 16 * c)));
            const float2 wwb = __ldg(reinterpret_cast<const float2*>(
                W + (size_t)5 * (LCOLS * 2) + 2 * (jB + 16 * c)));
            w0a[c] = wwa.x; w1a[c] = wwa.y;
            w0b[c] = wwb.x; w1b[c] = wwb.y;
        }
        bfly2<1>(Y, w0a, w1a);
        bfly2<2>(Y, w0b, w1b);
    }

    // ---- swap C : reg bit0 = j[6] ; stage 6 ----
    #pragma unroll
    for (int p = 0; p < NPAIR; ++p)
        bitswap2<1, 16>(Y[p], lo16);
    const int jC = (l & 15) + ((l >> 4) & 1) * 16 + w * 128;
    // j(c) = jC + (c&1)*64 + ((c>>1)&1)*32
    {
        #pragma unroll
        for (int c = 0; c < 4; ++c) {
            const int jb = jC + ((c & 1) << 6) + (((c >> 1) & 1) << 5);
            const float2 ww = __ldg(reinterpret_cast<const float2*>(
                W + (size_t)6 * (LCOLS * 2) + 2 * jb));
            w0a[c] = ww.x; w1a[c] = ww.y;
        }
        bfly2<1>(Y, w0a, w1a);
    }

    // ---- hoist round-1 weights (stages 7,8) above the barrier ----
    // lanes = j[0:4]; warp bits = (j5, j6, j9, j10, j11)
    const int base1 = l + (w & 1) * 32 + ((w >> 1) & 1) * 64
                    + ((w >> 2) & 1) * 512 + ((w >> 3) & 1) * 1024
                    + ((w >> 4) & 1) * 2048;            // j = base1 + 128c
    const int pb1 = phys(base1);                        // bit11 const, no carry
    #pragma unroll
    for (int c = 0; c < 4; ++c) {
        const float2 wwa = __ldg(reinterpret_cast<const float2*>(
            W + (size_t)7 * (LCOLS * 2) + 2 * (base1 + 128 * c)));
        const float2 wwb = __ldg(reinterpret_cast<const float2*>(
            W + (size_t)8 * (LCOLS * 2) + 2 * (base1 + 128 * c)));
        w0a[c] = wwa.x; w1a[c] = wwa.y;
        w0b[c] = wwb.x; w1b[c] = wwb.y;
    }

    // ---- store packed columns to smem at phys(j), 64-bit STS ----
    {
        int sj[4];
        #pragma unroll
        for (int c = 0; c < 4; ++c)
            sj[c] = phys(jC + ((c & 1) << 6) + (((c >> 1) & 1) << 5));
        #pragma unroll
        for (int p = 0; p < NPAIR; ++p)
            #pragma unroll
            for (int c = 0; c < 4; ++c)
                sm2[p * LCOLS + sj[c]] = Y[p][c];
    }
    __syncthreads();

    // ---- round 1 : stages 7,8 (regs = j[7:8]) ----
    {
        ull V[NPAIR][4];
        #pragma unroll
        for (int p = 0; p < NPAIR; ++p)
            #pragma unroll
            for (int c = 0; c < 4; ++c)
                V[p][c] = sm2[p * LCOLS + pb1 + 128 * c];

        bfly2<1>(V, w0a, w1a);
        bfly2<2>(V, w0b, w1b);

        // in-place writeback (each element owned by exactly this thread)
        #pragma unroll
        for (int p = 0; p < NPAIR; ++p)
            #pragma unroll
            for (int c = 0; c < 4; ++c)
                sm2[p * LCOLS + pb1 + 128 * c] = V[p][c];
    }

    // ---- hoist round-2 weights (stages 9,10) above the barrier ----
    // lanes = (j0..j3, j11); warp bits = j[4:8]
    const int base2 = (l & 15) + w * 16 + ((l >> 4) & 1) * 2048;  // j = base2 + 512c
    const int pb2 = base2 ^ (((l >> 4) & 1) << 4);                // phys, no carry
    #pragma unroll
    for (int c = 0; c < 4; ++c) {
        const float2 wwa = __ldg(reinterpret_cast<const float2*>(
            W + (size_t)9 * (LCOLS * 2) + 2 * (base2 + 512 * c)));
        const float2 wwb = __ldg(reinterpret_cast<const float2*>(
            W + (size_t)10 * (LCOLS * 2) + 2 * (base2 + 512 * c)));
        w0a[c] = wwa.x; w1a[c] = wwa.y;
        w0b[c] = wwb.x; w1b[c] = wwb.y;
    }
    __syncthreads();

    // ---- round 2 : stages 9,10 in-reg; swap j9<->j11; stage 11 in-reg ----
    {
        ull V[NPAIR][4];
        #pragma unroll
        for (int p = 0; p < NPAIR; ++p)
            #pragma unroll
            for (int c = 0; c < 4; ++c)
                V[p][c] = sm2[p * LCOLS + pb2 + 512 * c];

        bfly2<1>(V, w0a, w1a);

        // stage-11 weights: issue while stage-10 math runs (w0a now dead)
        // post-swap layout: c0 = j11 (off 2048), c1 = j10 (off 1024), l4 = j9
        const int b11m = (l & 15) + w * 16 + ((l >> 4) & 1) * 512;
        #pragma unroll
        for (int c = 0; c < 4; ++c) {
            const int jb = b11m + ((c & 1) << 11) + (((c >> 1) & 1) << 10);
            const float2 ww = __ldg(reinterpret_cast<const float2*>(
                W + (size_t)11 * (LCOLS * 2) + 2 * jb));
            w0a[c] = ww.x; w1a[c] = ww.y;
        }

        bfly2<2>(V, w0b, w1b);

        // swap reg bit0 (j9) <-> lane bit4 (j11); then stage 11 in-register
        #pragma unroll
        for (int p = 0; p < NPAIR; ++p)
            bitswap2<1, 16>(V[p], lo16);
        bfly2<1>(V, w0a, w1a);

        // direct global store: lanes 0-15 / 16-31 each cover 64B runs
        #pragma unroll
        for (int p = 0; p < NPAIR; ++p) {
            float* op0 = out + (size_t)(row0 + 2 * p) * LCOLS + b11m;
            float* op1 = out + (size_t)(row0 + 2 * p + 1) * LCOLS + b11m;
            #pragma unroll
            for (int c = 0; c < 4; ++c) {
                const int off = ((c & 1) << 11) + (((c >> 1) & 1) << 10);
                float a, b;
                unpack2(V[p][c], a, b);
                op0[off] = a;
                op1[off] = b;
            }
        }
    }
}

extern "C" void kernel_launch(void* const* d_in, const int* in_sizes, int n_in,
                              void* d_out, int out_size) {
    const float* x;
    const float* W;
    if (in_sizes[0] == NSTAGES * LCOLS * 2) {   // W has 98304 elements
        W = (const float*)d_in[0];
        x = (const float*)d_in[1];
    } else {
        x = (const float*)d_in[0];
        W = (const float*)d_in[1];
    }
    float* out = (float*)d_out;

    const int smem_bytes = NPAIR * LCOLS * sizeof(ull);  // 128 KB
    cudaFuncSetAttribute(butterfly_kernel,
                         cudaFuncAttributeMaxDynamicSharedMemorySize, smem_bytes);
    butterfly_kernel<<<NBATCH / RROWS, TPB, smem_bytes>>>(x, W, out);
}

// round 15
// speedup vs baseline: 1.2253x; 1.0310x over previous
#include <cuda_runtime.h>

#define LCOLS 4096
#define NSTAGES 12
#define RROWS 8
#define NPAIR 4
#define TPB 1024
#define NBATCH 8192

typedef unsigned long long ull;

// ---- packed f32x2 helpers (FFMA2/FMUL2 are PTX-only on sm_103a) ----
__device__ __forceinline__ ull pack2(float a, float b) {
    ull r; asm("mov.b64 %0, {%1, %2};" : "=l"(r) : "f"(a), "f"(b)); return r;
}
__device__ __forceinline__ void unpack2(ull v, float& a, float& b) {
    asm("mov.b64 {%0, %1}, %2;" : "=f"(a), "=f"(b) : "l"(v));
}
__device__ __forceinline__ ull dup2(float a) { return pack2(a, a); }
__device__ __forceinline__ ull mul2(ull a, ull b) {
    ull d; asm("mul.rn.f32x2 %0, %1, %2;" : "=l"(d) : "l"(a), "l"(b)); return d;
}
__device__ __forceinline__ ull fma2(ull a, ull b, ull c) {
    ull d; asm("fma.rn.f32x2 %0, %1, %2, %3;" : "=l"(d) : "l"(a), "l"(b), "l"(c)); return d;
}

// named-barrier helpers
__device__ __forceinline__ void nbar_sync(int id, int cnt) {
    asm volatile("bar.sync %0, %1;" :: "r"(id), "r"(cnt) : "memory");
}
__device__ __forceinline__ void nbar_arrive(int id, int cnt) {
    asm volatile("bar.arrive %0, %1;" :: "r"(id), "r"(cnt) : "memory");
}

// packed butterfly on reg-bit D over 4 regs; weights shared by both packed rows
template <int D>
__device__ __forceinline__ void bfly2(ull Y[NPAIR][4],
                                      const float* w0, const float* w1) {
    #pragma unroll
    for (int c = 0; c < 4; ++c) {
        if (c & D) continue;
        const int ch = c | D;
        const ull W0l = dup2(w0[c]),  W1l = dup2(w1[c]);
        const ull W0h = dup2(w0[ch]), W1h = dup2(w1[ch]);
        #pragma unroll
        for (int p = 0; p < NPAIR; ++p) {
            const ull a = Y[p][c], b = Y[p][ch];
            Y[p][c]  = fma2(W0l, a, mul2(W1l, b));
            Y[p][ch] = fma2(W0h, b, mul2(W1h, a));
        }
    }
}

// swap roles of register bit MC and lane bit ML (half-exchange, 2 shfl / 4 regs)
template <int MC, int ML>
__device__ __forceinline__ void bitswap2(ull* yr, bool lo) {
    #pragma unroll
    for (int c = 0; c < 4; ++c) {
        if (c & MC) continue;
        const int ch = c | MC;
        ull send = lo ? yr[ch] : yr[c];
        ull recv = __shfl_xor_sync(0xffffffffu, send, ML);
        if (lo) yr[ch] = recv; else yr[c] = recv;
    }
}

// shared-memory physical swizzle: bank bit 4 ^= address bit 11
__device__ __forceinline__ int phys(int a) {
    return a ^ (((a >> 11) & 1) << 4);
}

// y[j] <- W[s][j][0]*y[j] + W[s][j][1]*y[j ^ (1<<s)]
// TPB=1024, thread owns 4 cols, row-pairs packed in f32x2, 64-bit smem words.
// Weight loads software-pipelined; block-wide __syncthreads replaced with
// minimal-scope named barriers:
//  T1: phase-1 store (warp bits j7..j11) -> round-1 gather (j9..j11 = warp
//      bits 2-4): producer set == consumer set == 4 warps sharing w>>2.
//  T2: round-1 writeback (j5,j6 = warp bits 0,1) -> round-2 gather (j5,j6 =
//      warp bits 1,2): arrive on 8+(w&3), sync on 8+((w>>1)&3), count 512.
__global__ __launch_bounds__(TPB, 1)
void butterfly_kernel(const float* __restrict__ x,
                      const float* __restrict__ W,
                      float* __restrict__ out)
{
    extern __shared__ ull sm2[];   // NPAIR * LCOLS ulls = 128 KB
    const int tid  = threadIdx.x;
    const int row0 = blockIdx.x * RROWS;
    const int l    = tid & 31;
    const int w    = tid >> 5;
    const int j0   = tid * 4;
    const bool lo1  = (l & 1) == 0;
    const bool lo2  = (l & 2) == 0;
    const bool lo4  = (l & 4) == 0;
    const bool lo8  = (l & 8) == 0;
    const bool lo16 = (l & 16) == 0;

    ull Y[NPAIR][4];

    // ---- load 8 rows x 4 contiguous cols, pack row-pairs ----
    #pragma unroll
    for (int p = 0; p < NPAIR; ++p) {
        float4 a0 = __ldg(reinterpret_cast<const float4*>(
            x + (size_t)(row0 + 2 * p) * LCOLS + j0));
        float4 a1 = __ldg(reinterpret_cast<const float4*>(
            x + (size_t)(row0 + 2 * p + 1) * LCOLS + j0));
        Y[p][0] = pack2(a0.x, a1.x); Y[p][1] = pack2(a0.y, a1.y);
        Y[p][2] = pack2(a0.z, a1.z); Y[p][3] = pack2(a0.w, a1.w);
    }

    float w0a[4], w1a[4], w0b[4], w1b[4];

    // ---- stages 0,1 : regs = j[0:1]; both stages' weights issued first ----
    {
        const float4* wp0 = reinterpret_cast<const float4*>(W + (size_t)j0 * 2);
        const float4* wp1 = reinterpret_cast<const float4*>(
            W + (size_t)1 * (LCOLS * 2) + j0 * 2);
        float4 A0 = __ldg(wp0), B0 = __ldg(wp0 + 1);
        float4 A1 = __ldg(wp1), B1 = __ldg(wp1 + 1);
        w0a[0]=A0.x; w1a[0]=A0.y; w0a[1]=A0.z; w1a[1]=A0.w;
        w0a[2]=B0.x; w1a[2]=B0.y; w0a[3]=B0.z; w1a[3]=B0.w;
        w0b[0]=A1.x; w1b[0]=A1.y; w0b[1]=A1.z; w1b[1]=A1.w;
        w0b[2]=B1.x; w1b[2]=B1.y; w0b[3]=B1.z; w1b[3]=B1.w;
        bfly2<1>(Y, w0a, w1a);
        bfly2<2>(Y, w0b, w1b);
    }

    // ---- swap A : regs = j[2:3] ; stages 2,3 (weights paired) ----
    #pragma unroll
    for (int p = 0; p < NPAIR; ++p) {
        bitswap2<1, 1>(Y[p], lo1);
        bitswap2<2, 2>(Y[p], lo2);
    }
    const int jA = (l & 3) + ((l >> 2) & 7) * 16 + w * 128;   // j = jA + 4c
    {
        #pragma unroll
        for (int c = 0; c < 4; ++c) {
            const float2 wwa = __ldg(reinterpret_cast<const float2*>(
                W + (size_t)2 * (LCOLS * 2) + 2 * (jA + 4 * c)));
            const float2 wwb = __ldg(reinterpret_cast<const float2*>(
                W + (size_t)3 * (LCOLS * 2) + 2 * (jA + 4 * c)));
            w0a[c] = wwa.x; w1a[c] = wwa.y;
            w0b[c] = wwb.x; w1b[c] = wwb.y;
        }
        bfly2<1>(Y, w0a, w1a);
        bfly2<2>(Y, w0b, w1b);
    }

    // ---- swap B : regs = j[4:5] ; stages 4,5 (weights paired) ----
    #pragma unroll
    for (int p = 0; p < NPAIR; ++p) {
        bitswap2<1, 4>(Y[p], lo4);
        bitswap2<2, 8>(Y[p], lo8);
    }
    const int jB = (l & 15) + ((l >> 4) & 1) * 64 + w * 128;  // j = jB + 16c
    {
        #pragma unroll
        for (int c = 0; c < 4; ++c) {
            const float2 wwa = __ldg(reinterpret_cast<const float2*>(
                W + (size_t)4 * (LCOLS * 2) + 2 * (jB + 16 * c)));
            const float2 wwb = __ldg(reinterpret_cast<const float2*>(
                W + (size_t)5 * (LCOLS * 2) + 2 * (jB + 16 * c)));
            w0a[c] = wwa.x; w1a[c] = wwa.y;
            w0b[c] = wwb.x; w1b[c] = wwb.y;
        }
        bfly2<1>(Y, w0a, w1a);
        bfly2<2>(Y, w0b, w1b);
    }

    // ---- swap C : reg bit0 = j[6] ; stage 6 ----
    #pragma unroll
    for (int p = 0; p < NPAIR; ++p)
        bitswap2<1, 16>(Y[p], lo16);
    const int jC = (l & 15) + ((l >> 4) & 1) * 16 + w * 128;
    // j(c) = jC + (c&1)*64 + ((c>>1)&1)*32 ; warp bits w = (j7..j11)
    {
        #pragma unroll
        for (int c = 0; c < 4; ++c) {
            const int jb = jC + ((c & 1) << 6) + (((c >> 1) & 1) << 5);
            const float2 ww = __ldg(reinterpret_cast<const float2*>(
                W + (size_t)6 * (LCOLS * 2) + 2 * jb));
            w0a[c] = ww.x; w1a[c] = ww.y;
        }
        bfly2<1>(Y, w0a, w1a);
    }

    // ---- hoist round-1 weights (stages 7,8) ahead of the barrier ----
    // round-1: lanes = j[0:4]; warp bits = (j5, j6, j9, j10, j11)
    const int base1 = l + (w & 1) * 32 + ((w >> 1) & 1) * 64
                    + ((w >> 2) & 1) * 512 + ((w >> 3) & 1) * 1024
                    + ((w >> 4) & 1) * 2048;            // j = base1 + 128c
    const int pb1 = phys(base1);                        // bit11 const, no carry
    #pragma unroll
    for (int c = 0; c < 4; ++c) {
        const float2 wwa = __ldg(reinterpret_cast<const float2*>(
            W + (size_t)7 * (LCOLS * 2) + 2 * (base1 + 128 * c)));
        const float2 wwb = __ldg(reinterpret_cast<const float2*>(
            W + (size_t)8 * (LCOLS * 2) + 2 * (base1 + 128 * c)));
        w0a[c] = wwa.x; w1a[c] = wwa.y;
        w0b[c] = wwb.x; w1b[c] = wwb.y;
    }

    // ---- store packed columns to smem at phys(j), 64-bit STS ----
    {
        int sj[4];
        #pragma unroll
        for (int c = 0; c < 4; ++c)
            sj[c] = phys(jC + ((c & 1) << 6) + (((c >> 1) & 1) << 5));
        #pragma unroll
        for (int p = 0; p < NPAIR; ++p)
            #pragma unroll
            for (int c = 0; c < 4; ++c)
                sm2[p * LCOLS + sj[c]] = Y[p][c];
    }

    // T1: phase-1 (j9..j11 = w bits 2-4) producers == round-1 consumers
    nbar_sync(w >> 2, 128);

    // ---- round 1 : stages 7,8 (regs = j[7:8]) ----
    {
        ull V[NPAIR][4];
        #pragma unroll
        for (int p = 0; p < NPAIR; ++p)
            #pragma unroll
            for (int c = 0; c < 4; ++c)
                V[p][c] = sm2[p * LCOLS + pb1 + 128 * c];

        bfly2<1>(V, w0a, w1a);
        bfly2<2>(V, w0b, w1b);

        // in-place writeback (each element owned by exactly this thread)
        #pragma unroll
        for (int p = 0; p < NPAIR; ++p)
            #pragma unroll
            for (int c = 0; c < 4; ++c)
                sm2[p * LCOLS + pb1 + 128 * c] = V[p][c];
    }

    // ---- hoist round-2 weights (stages 9,10) ahead of the barrier ----
    // round-2: lanes = (j0..j3, j11); warp bits = j[4:8]
    const int base2 = (l & 15) + w * 16 + ((l >> 4) & 1) * 2048;  // j = base2 + 512c
    const int pb2 = base2 ^ (((l >> 4) & 1) << 4);                // phys, no carry
    #pragma unroll
    for (int c = 0; c < 4; ++c) {
        const float2 wwa = __ldg(reinterpret_cast<const float2*>(
            W + (size_t)9 * (LCOLS * 2) + 2 * (base2 + 512 * c)));
        const float2 wwb = __ldg(reinterpret_cast<const float2*>(
            W + (size_t)10 * (LCOLS * 2) + 2 * (base2 + 512 * c)));
        w0a[c] = wwa.x; w1a[c] = wwa.y;
        w0b[c] = wwb.x; w1b[c] = wwb.y;
    }

    // T2: round-1 writers of (j5,j6)=(w0,w1) -> round-2 readers of (j5,j6)=(w1,w2)
    // arrive (non-blocking) precedes every sync -> no deadlock; count 256+256.
    nbar_arrive(8 + (w & 3), 512);
    nbar_sync(8 + ((w >> 1) & 3), 512);

    // ---- round 2 : stages 9,10 in-reg; swap j9<->j11; stage 11 in-reg ----
    {
        ull V[NPAIR][4];
        #pragma unroll
        for (int p = 0; p < NPAIR; ++p)
            #pragma unroll
            for (int c = 0; c < 4; ++c)
                V[p][c] = sm2[p * LCOLS + pb2 + 512 * c];

        bfly2<1>(V, w0a, w1a);

        // stage-11 weights: issue while stage-10 math runs (w0a now dead)
        // post-swap layout: c0 = j11 (off 2048), c1 = j10 (off 1024), l4 = j9
        const int b11m = (l & 15) + w * 16 + ((l >> 4) & 1) * 512;
        #pragma unroll
        for (int c = 0; c < 4; ++c) {
            const int jb = b11m + ((c & 1) << 11) + (((c >> 1) & 1) << 10);
            const float2 ww = __ldg(reinterpret_cast<const float2*>(
                W + (size_t)11 * (LCOLS * 2) + 2 * jb));
            w0a[c] = ww.x; w1a[c] = ww.y;
        }

        bfly2<2>(V, w0b, w1b);

        // swap reg bit0 (j9) <-> lane bit4 (j11); then stage 11 in-register
        #pragma unroll
        for (int p = 0; p < NPAIR; ++p)
            bitswap2<1, 16>(V[p], lo16);
        bfly2<1>(V, w0a, w1a);

        // direct global store: lanes 0-15 / 16-31 each cover 64B runs
        #pragma unroll
        for (int p = 0; p < NPAIR; ++p) {
            float* op0 = out + (size_t)(row0 + 2 * p) * LCOLS + b11m;
            float* op1 = out + (size_t)(row0 + 2 * p + 1) * LCOLS + b11m;
            #pragma unroll
            for (int c = 0; c < 4; ++c) {
                const int off = ((c & 1) << 11) + (((c >> 1) & 1) << 10);
                float a, b;
                unpack2(V[p][c], a, b);
                op0[off] = a;
                op1[off] = b;
            }
        }
    }
}

extern "C" void kernel_launch(void* const* d_in, const int* in_sizes, int n_in,
                              void* d_out, int out_size) {
    const float* x;
    const float* W;
    if (in_sizes[0] == NSTAGES * LCOLS * 2) {   // W has 98304 elements
        W = (const float*)d_in[0];
        x = (const float*)d_in[1];
    } else {
        x = (const float*)d_in[0];
        W = (const float*)d_in[1];
    }
    float* out = (float*)d_out;

    const int smem_bytes = NPAIR * LCOLS * sizeof(ull);  // 128 KB
    cudaFuncSetAttribute(butterfly_kernel,
                         cudaFuncAttributeMaxDynamicSharedMemorySize, smem_bytes);
    butterfly_kernel<<<NBATCH / RROWS, TPB, smem_bytes>>>(x, W, out);
}